// round 7
// baseline (speedup 1.0000x reference)
#include <cuda_runtime.h>
#include <cuda_fp16.h>
#include <cstdint>

// QuantizedLinearINT4 (sm_103 base target -> legacy mma.sync path).
// Prolog: dequant W(int4 packed)->fp16 g_wh [N,K]; x f32->fp16 g_xh [M,K].
// GEMM: CTA 128x256, 8 warps (2x4), warp tile 64x64, BK=64,
//       4-stage cp.async pipeline, ONE sync per chunk (wait->sync->issue->compute),
//       ldmatrix.x4 feeds, mma.m16n8k16 f32 accum.
// out[M,N] f32 = x @ W^T + bias.

#define KDIM 4096
#define NDIM 11008
#define MDIM 8192
#define BM 128
#define BN 256
#define BK 64                    // halves per k-chunk (128 B rows)
#define NCHUNKS (KDIM / BK)      // 64
#define THREADS 256
#define STAGES 4

#define A_STAGE_BYTES (BM * 128)                      // 16 KB
#define B_STAGE_BYTES (BN * 128)                      // 32 KB
#define STAGE_BYTES (A_STAGE_BYTES + B_STAGE_BYTES)   // 48 KB
#define SMEM_TOTAL (STAGES * STAGE_BYTES)             // 192 KB

__device__ __half g_xh[(size_t)MDIM * KDIM];   // 64 MB
__device__ __half g_wh[(size_t)NDIM * KDIM];   // 90 MB

// ---------------- prolog kernels ----------------

__global__ void convert_x_kernel(const float* __restrict__ x) {
    size_t i = (size_t)blockIdx.x * blockDim.x + threadIdx.x;  // one float4
    float4 v = ((const float4*)x)[i];
    __half2* o = (__half2*)g_xh;
    o[2 * i]     = __floats2half2_rn(v.x, v.y);
    o[2 * i + 1] = __floats2half2_rn(v.z, v.w);
}

__global__ void dequant_w_kernel(const int* __restrict__ wp,
                                 const float* __restrict__ scales) {
    size_t i = (size_t)blockIdx.x * blockDim.x + threadIdx.x;  // int32 index
    int n  = (int)(i >> 11);         // K/2 = 2048 int32 per row
    int k2 = (int)(i & 2047);
    int v  = wp[i];
    float s = scales[(n << 5) + (k2 >> 6)];   // group = 128 halves = 64 int32
    float lo = (float)((v & 15) - 8) * s;
    float hi = (float)(((v >> 4) & 15) - 8) * s;
    ((__half2*)g_wh)[i] = __floats2half2_rn(lo, hi);
}

// ---------------- helpers ----------------

__device__ __forceinline__ uint32_t smem_u32(const void* p) {
    return (uint32_t)__cvta_generic_to_shared(p);
}
__device__ __forceinline__ uint32_t sw128(uint32_t off) {
    return off ^ ((off >> 3) & 0x70);
}
__device__ __forceinline__ void cp_async16(uint32_t saddr, const void* gaddr) {
    asm volatile("cp.async.cg.shared.global [%0], [%1], 16;"
                 :: "r"(saddr), "l"(gaddr));
}
__device__ __forceinline__ void cp_commit() {
    asm volatile("cp.async.commit_group;");
}
template <int N>
__device__ __forceinline__ void cp_wait() {
    asm volatile("cp.async.wait_group %0;" :: "n"(N));
}
__device__ __forceinline__ void ldsm4(uint32_t addr, uint32_t& r0, uint32_t& r1,
                                      uint32_t& r2, uint32_t& r3) {
    asm volatile("ldmatrix.sync.aligned.m8n8.x4.shared.b16 {%0,%1,%2,%3}, [%4];"
                 : "=r"(r0), "=r"(r1), "=r"(r2), "=r"(r3) : "r"(addr));
}

// ---------------- GEMM kernel ----------------

__global__ __launch_bounds__(THREADS, 1)
void q4_mma_kernel(const float* __restrict__ bias, float* __restrict__ out) {
    extern __shared__ char smem[];
    const uint32_t sbase = smem_u32(smem);

    const int tid  = threadIdx.x;
    const int wid  = tid >> 5;
    const int lane = tid & 31;
    const int g    = lane >> 2;
    const int tig  = lane & 3;
    const int warpM = wid >> 2;     // 0..1, 64 rows each
    const int warpN = wid & 3;      // 0..3, 64 cols each

    const int m0 = blockIdx.x * BM; // m fastest -> g_xh L2-resident per wave
    const int n0 = blockIdx.y * BN;

    // cp.async mapping: 16B chunks; 256 threads cover 32 rows x 8 segs per step
    const int crow = tid >> 3;      // 0..31
    const int cseg = tid & 7;       // 16B segment within 128B row
    const __half* aG = g_xh + (size_t)(m0 + crow) * KDIM + cseg * 8;
    const __half* bG = g_wh + (size_t)(n0 + crow) * KDIM + cseg * 8;

    uint32_t aS[4], bS[8];
#pragma unroll
    for (int i = 0; i < 4; i++)
        aS[i] = sw128((uint32_t)((crow + 32 * i) * 128 + cseg * 16));
#pragma unroll
    for (int i = 0; i < 8; i++)
        bS[i] = sw128((uint32_t)((crow + 32 * i) * 128 + cseg * 16));

    auto issue = [&](int kc) {
        const int st = kc % STAGES;
        const uint32_t sa = sbase + st * STAGE_BYTES;
        const uint32_t sb = sa + A_STAGE_BYTES;
        const size_t gofs = (size_t)kc * BK;
#pragma unroll
        for (int i = 0; i < 4; i++)
            cp_async16(sa + aS[i], aG + (size_t)(32 * i) * KDIM + gofs);
#pragma unroll
        for (int i = 0; i < 8; i++)
            cp_async16(sb + bS[i], bG + (size_t)(32 * i) * KDIM + gofs);
        cp_commit();
    };

    // ldmatrix address components (stage-relative)
    const uint32_t aRow = (uint32_t)(warpM * 64 + (lane & 15));
    const uint32_t aKof = (uint32_t)((lane >> 4) * 16);
    const uint32_t bRow = (uint32_t)(warpN * 64 + ((lane >> 4) << 3) + (lane & 7));
    const uint32_t bKof = (uint32_t)(((lane >> 3) & 1) * 16);

    float acc[4][8][4];
#pragma unroll
    for (int i = 0; i < 4; i++)
#pragma unroll
        for (int j = 0; j < 8; j++)
#pragma unroll
            for (int c = 0; c < 4; c++) acc[i][j][c] = 0.0f;

    // prologue: fill pipeline
    issue(0); issue(1); issue(2);

#pragma unroll 1
    for (int kc = 0; kc < NCHUNKS; kc++) {
        cp_wait<2>();
        __syncthreads();            // data visible to all; all warps past chunk kc-1
        if (kc + 3 < NCHUNKS) issue(kc + 3);   // refills stage (kc-1)%4: vacated

        const int st = kc % STAGES;
        const uint32_t sa = sbase + st * STAGE_BYTES;
        const uint32_t sb = sa + A_STAGE_BYTES;

#pragma unroll
        for (int ks = 0; ks < 4; ks++) {
            uint32_t a[4][4], b[4][4];
#pragma unroll
            for (int mi = 0; mi < 4; mi++) {
                uint32_t off = (aRow + mi * 16) * 128 + ks * 32 + aKof;
                ldsm4(sa + sw128(off), a[mi][0], a[mi][1], a[mi][2], a[mi][3]);
            }
#pragma unroll
            for (int nj = 0; nj < 4; nj++) {
                uint32_t off = (bRow + nj * 16) * 128 + ks * 32 + bKof;
                ldsm4(sb + sw128(off), b[nj][0], b[nj][1], b[nj][2], b[nj][3]);
            }
#pragma unroll
            for (int mi = 0; mi < 4; mi++) {
#pragma unroll
                for (int nj = 0; nj < 4; nj++) {
                    asm volatile(
                        "mma.sync.aligned.m16n8k16.row.col.f32.f16.f16.f32 "
                        "{%0,%1,%2,%3}, {%4,%5,%6,%7}, {%8,%9}, {%0,%1,%2,%3};\n"
                        : "+f"(acc[mi][2 * nj][0]), "+f"(acc[mi][2 * nj][1]),
                          "+f"(acc[mi][2 * nj][2]), "+f"(acc[mi][2 * nj][3])
                        : "r"(a[mi][0]), "r"(a[mi][1]), "r"(a[mi][2]), "r"(a[mi][3]),
                          "r"(b[nj][0]), "r"(b[nj][1]));
                    asm volatile(
                        "mma.sync.aligned.m16n8k16.row.col.f32.f16.f16.f32 "
                        "{%0,%1,%2,%3}, {%4,%5,%6,%7}, {%8,%9}, {%0,%1,%2,%3};\n"
                        : "+f"(acc[mi][2 * nj + 1][0]), "+f"(acc[mi][2 * nj + 1][1]),
                          "+f"(acc[mi][2 * nj + 1][2]), "+f"(acc[mi][2 * nj + 1][3])
                        : "r"(a[mi][0]), "r"(a[mi][1]), "r"(a[mi][2]), "r"(a[mi][3]),
                          "r"(b[nj][2]), "r"(b[nj][3]));
                }
            }
        }
    }

    // ---- epilogue: add bias, write f32 ----
#pragma unroll
    for (int mi = 0; mi < 4; mi++) {
        const int row = m0 + warpM * 64 + mi * 16 + g;
#pragma unroll
        for (int nj = 0; nj < 8; nj++) {
            const int col = n0 + warpN * 64 + nj * 8 + tig * 2;
            float2 bb = *(const float2*)(bias + col);
            float2 r0 = make_float2(acc[mi][nj][0] + bb.x, acc[mi][nj][1] + bb.y);
            float2 r1 = make_float2(acc[mi][nj][2] + bb.x, acc[mi][nj][3] + bb.y);
            *(float2*)(out + (size_t)row * NDIM + col)       = r0;
            *(float2*)(out + (size_t)(row + 8) * NDIM + col) = r1;
        }
    }
}

// ---------------- launcher ----------------

extern "C" void kernel_launch(void* const* d_in, const int* in_sizes, int n_in,
                              void* d_out, int out_size)
{
    const float* x      = (const float*)d_in[0];
    const int*   wp     = (const int*)d_in[1];
    const float* scales = (const float*)d_in[2];
    const float* bias   = (const float*)d_in[3];
    float*       out    = (float*)d_out;

    convert_x_kernel<<<(MDIM * (size_t)KDIM / 4) / 256, 256>>>(x);
    dequant_w_kernel<<<(NDIM * (size_t)(KDIM / 2)) / 256, 256>>>(wp, scales);

    static bool attr_set = false;
    if (!attr_set) {
        cudaFuncSetAttribute(q4_mma_kernel,
                             cudaFuncAttributeMaxDynamicSharedMemorySize, SMEM_TOTAL);
        attr_set = true;
    }
    dim3 grid(MDIM / BM, NDIM / BN);   // (64, 43), m fastest
    q4_mma_kernel<<<grid, THREADS, SMEM_TOTAL>>>(bias, out);
}

// round 8
// speedup vs baseline: 1.0235x; 1.0235x over previous
#include <cuda_runtime.h>
#include <cuda_fp16.h>
#include <cstdint>

// QuantizedLinearINT4 (sm_103 base target -> legacy mma.sync path).
// Prolog: dequant W(int4 packed)->fp16 g_wh [N,K]; x f32->fp16 g_xh [M,K].
// GEMM: CTA 128x256, 16 warps (4x4), warp tile 32x64, BK=64,
//       4-stage cp.async pipeline, one sync per chunk (wait->sync->issue->compute),
//       cp.async issuance spread across the ks loop, ldmatrix.x4 feeds,
//       mma.m16n8k16 f32 accum.  out[M,N] f32 = x @ W^T + bias.

#define KDIM 4096
#define NDIM 11008
#define MDIM 8192
#define BM 128
#define BN 256
#define BK 64                    // halves per k-chunk (128 B rows)
#define NCHUNKS (KDIM / BK)      // 64
#define THREADS 512
#define STAGES 4

#define A_STAGE_BYTES (BM * 128)                      // 16 KB
#define B_STAGE_BYTES (BN * 128)                      // 32 KB
#define STAGE_BYTES (A_STAGE_BYTES + B_STAGE_BYTES)   // 48 KB
#define SMEM_TOTAL (STAGES * STAGE_BYTES)             // 192 KB

__device__ __half g_xh[(size_t)MDIM * KDIM];   // 64 MB
__device__ __half g_wh[(size_t)NDIM * KDIM];   // 90 MB

// ---------------- prolog kernels ----------------

__global__ void convert_x_kernel(const float* __restrict__ x) {
    size_t i = (size_t)blockIdx.x * blockDim.x + threadIdx.x;  // one float4
    float4 v = ((const float4*)x)[i];
    __half2* o = (__half2*)g_xh;
    o[2 * i]     = __floats2half2_rn(v.x, v.y);
    o[2 * i + 1] = __floats2half2_rn(v.z, v.w);
}

__global__ void dequant_w_kernel(const int* __restrict__ wp,
                                 const float* __restrict__ scales) {
    size_t i = (size_t)blockIdx.x * blockDim.x + threadIdx.x;  // 4 int32 per thread
    size_t base = i * 4;
    int n  = (int)(base >> 11);        // K/2 = 2048 int32 per row
    int k2 = (int)(base & 2047);
    int4 v4 = ((const int4*)wp)[i];
    float s = scales[(n << 5) + (k2 >> 6)];   // 4 int32 never straddle a group (64 int32)
    __half2* o = (__half2*)g_wh + base;
    int vv[4] = {v4.x, v4.y, v4.z, v4.w};
#pragma unroll
    for (int j = 0; j < 4; j++) {
        int v = vv[j];
        float lo = (float)((v & 15) - 8) * s;
        float hi = (float)(((v >> 4) & 15) - 8) * s;
        o[j] = __floats2half2_rn(lo, hi);
    }
}

// ---------------- helpers ----------------

__device__ __forceinline__ uint32_t smem_u32(const void* p) {
    return (uint32_t)__cvta_generic_to_shared(p);
}
__device__ __forceinline__ uint32_t sw128(uint32_t off) {
    return off ^ ((off >> 3) & 0x70);
}
__device__ __forceinline__ void cp_async16(uint32_t saddr, const void* gaddr) {
    asm volatile("cp.async.cg.shared.global [%0], [%1], 16;"
                 :: "r"(saddr), "l"(gaddr));
}
__device__ __forceinline__ void cp_commit() {
    asm volatile("cp.async.commit_group;");
}
template <int N>
__device__ __forceinline__ void cp_wait() {
    asm volatile("cp.async.wait_group %0;" :: "n"(N));
}
__device__ __forceinline__ void ldsm4(uint32_t addr, uint32_t& r0, uint32_t& r1,
                                      uint32_t& r2, uint32_t& r3) {
    asm volatile("ldmatrix.sync.aligned.m8n8.x4.shared.b16 {%0,%1,%2,%3}, [%4];"
                 : "=r"(r0), "=r"(r1), "=r"(r2), "=r"(r3) : "r"(addr));
}

// ---------------- GEMM kernel ----------------

__global__ __launch_bounds__(THREADS, 1)
void q4_mma_kernel(const float* __restrict__ bias, float* __restrict__ out) {
    extern __shared__ char smem[];
    const uint32_t sbase = smem_u32(smem);

    const int tid  = threadIdx.x;
    const int wid  = tid >> 5;
    const int lane = tid & 31;
    const int g    = lane >> 2;
    const int tig  = lane & 3;
    const int warpM = wid >> 2;     // 0..3, 32 rows each
    const int warpN = wid & 3;      // 0..3, 64 cols each

    const int m0 = blockIdx.x * BM; // m fastest -> g_xh L2-resident per wave
    const int n0 = blockIdx.y * BN;

    // cp.async mapping: 16B chunks; 512 threads cover 64 rows x 8 segs
    const int crow = tid >> 3;      // 0..63
    const int cseg = tid & 7;       // 16B segment within 128B row
    const __half* aG = g_xh + (size_t)(m0 + crow) * KDIM + cseg * 8;
    const __half* bG = g_wh + (size_t)(n0 + crow) * KDIM + cseg * 8;

    uint32_t aS[2], bS[4];
#pragma unroll
    for (int i = 0; i < 2; i++)
        aS[i] = sw128((uint32_t)((crow + 64 * i) * 128 + cseg * 16));
#pragma unroll
    for (int i = 0; i < 4; i++)
        bS[i] = sw128((uint32_t)((crow + 64 * i) * 128 + cseg * 16));

    auto issueA = [&](int kc) {
        const uint32_t sa = sbase + (kc % STAGES) * STAGE_BYTES;
        const size_t gofs = (size_t)kc * BK;
#pragma unroll
        for (int i = 0; i < 2; i++)
            cp_async16(sa + aS[i], aG + (size_t)(64 * i) * KDIM + gofs);
    };
    auto issueB = [&](int kc, int half) {
        const uint32_t sb = sbase + (kc % STAGES) * STAGE_BYTES + A_STAGE_BYTES;
        const size_t gofs = (size_t)kc * BK;
#pragma unroll
        for (int i = 0; i < 2; i++)
            cp_async16(sb + bS[half * 2 + i],
                       bG + (size_t)(64 * (half * 2 + i)) * KDIM + gofs);
    };

    // ldmatrix address components (stage-relative)
    const uint32_t aRow = (uint32_t)(warpM * 32 + (lane & 15));
    const uint32_t aKof = (uint32_t)((lane >> 4) * 16);
    const uint32_t bRow = (uint32_t)(warpN * 64 + ((lane >> 4) << 3) + (lane & 7));
    const uint32_t bKof = (uint32_t)(((lane >> 3) & 1) * 16);

    float acc[2][8][4];
#pragma unroll
    for (int i = 0; i < 2; i++)
#pragma unroll
        for (int j = 0; j < 8; j++)
#pragma unroll
            for (int c = 0; c < 4; c++) acc[i][j][c] = 0.0f;

    // prologue: fill pipeline (3 chunks, one commit group each)
    issueA(0); issueB(0, 0); issueB(0, 1); cp_commit();
    issueA(1); issueB(1, 0); issueB(1, 1); cp_commit();
    issueA(2); issueB(2, 0); issueB(2, 1); cp_commit();

#pragma unroll 1
    for (int kc = 0; kc < NCHUNKS; kc++) {
        cp_wait<2>();
        __syncthreads();            // chunk kc visible; all warps past chunk kc-1
        const bool doIssue = (kc + 3 < NCHUNKS);   // refills stage (kc-1)%4: vacated

        const int st = kc % STAGES;
        const uint32_t sa = sbase + st * STAGE_BYTES;
        const uint32_t sb = sa + A_STAGE_BYTES;

#pragma unroll
        for (int ks = 0; ks < 4; ks++) {
            uint32_t a[2][4], b[4][4];
#pragma unroll
            for (int mi = 0; mi < 2; mi++) {
                uint32_t off = (aRow + mi * 16) * 128 + ks * 32 + aKof;
                ldsm4(sa + sw128(off), a[mi][0], a[mi][1], a[mi][2], a[mi][3]);
            }
#pragma unroll
            for (int nj = 0; nj < 4; nj++) {
                uint32_t off = (bRow + nj * 16) * 128 + ks * 32 + bKof;
                ldsm4(sb + sw128(off), b[nj][0], b[nj][1], b[nj][2], b[nj][3]);
            }
            // spread next-chunk cp.async across the ks loop
            if (doIssue) {
                if (ks == 0) issueA(kc + 3);
                else if (ks == 1) issueB(kc + 3, 0);
                else if (ks == 2) { issueB(kc + 3, 1); cp_commit(); }
            }
#pragma unroll
            for (int mi = 0; mi < 2; mi++) {
#pragma unroll
                for (int nj = 0; nj < 4; nj++) {
                    asm volatile(
                        "mma.sync.aligned.m16n8k16.row.col.f32.f16.f16.f32 "
                        "{%0,%1,%2,%3}, {%4,%5,%6,%7}, {%8,%9}, {%0,%1,%2,%3};\n"
                        : "+f"(acc[mi][2 * nj][0]), "+f"(acc[mi][2 * nj][1]),
                          "+f"(acc[mi][2 * nj][2]), "+f"(acc[mi][2 * nj][3])
                        : "r"(a[mi][0]), "r"(a[mi][1]), "r"(a[mi][2]), "r"(a[mi][3]),
                          "r"(b[nj][0]), "r"(b[nj][1]));
                    asm volatile(
                        "mma.sync.aligned.m16n8k16.row.col.f32.f16.f16.f32 "
                        "{%0,%1,%2,%3}, {%4,%5,%6,%7}, {%8,%9}, {%0,%1,%2,%3};\n"
                        : "+f"(acc[mi][2 * nj + 1][0]), "+f"(acc[mi][2 * nj + 1][1]),
                          "+f"(acc[mi][2 * nj + 1][2]), "+f"(acc[mi][2 * nj + 1][3])
                        : "r"(a[mi][0]), "r"(a[mi][1]), "r"(a[mi][2]), "r"(a[mi][3]),
                          "r"(b[nj][2]), "r"(b[nj][3]));
                }
            }
        }
    }

    // ---- epilogue: add bias, write f32 ----
#pragma unroll
    for (int mi = 0; mi < 2; mi++) {
        const int row = m0 + warpM * 32 + mi * 16 + g;
#pragma unroll
        for (int nj = 0; nj < 8; nj++) {
            const int col = n0 + warpN * 64 + nj * 8 + tig * 2;
            float2 bb = *(const float2*)(bias + col);
            float2 r0 = make_float2(acc[mi][nj][0] + bb.x, acc[mi][nj][1] + bb.y);
            float2 r1 = make_float2(acc[mi][nj][2] + bb.x, acc[mi][nj][3] + bb.y);
            *(float2*)(out + (size_t)row * NDIM + col)       = r0;
            *(float2*)(out + (size_t)(row + 8) * NDIM + col) = r1;
        }
    }
}

// ---------------- launcher ----------------

extern "C" void kernel_launch(void* const* d_in, const int* in_sizes, int n_in,
                              void* d_out, int out_size)
{
    const float* x      = (const float*)d_in[0];
    const int*   wp     = (const int*)d_in[1];
    const float* scales = (const float*)d_in[2];
    const float* bias   = (const float*)d_in[3];
    float*       out    = (float*)d_out;

    convert_x_kernel<<<(MDIM * (size_t)KDIM / 4) / 256, 256>>>(x);
    dequant_w_kernel<<<(NDIM * (size_t)(KDIM / 2) / 4) / 256, 256>>>(wp, scales);

    static bool attr_set = false;
    if (!attr_set) {
        cudaFuncSetAttribute(q4_mma_kernel,
                             cudaFuncAttributeMaxDynamicSharedMemorySize, SMEM_TOTAL);
        attr_set = true;
    }
    dim3 grid(MDIM / BM, NDIM / BN);   // (64, 43), m fastest
    q4_mma_kernel<<<grid, THREADS, SMEM_TOTAL>>>(bias, out);
}

// round 9
// speedup vs baseline: 1.1058x; 1.0804x over previous
#include <cuda_runtime.h>
#include <cuda_fp16.h>
#include <cstdint>

// QuantizedLinearINT4 (sm_103 base target -> legacy mma.sync path).
// Prolog: dequant W(int4 packed)->fp16 g_wh [N,K]; x f32->fp16 g_xh [M,K].
// GEMM: CTA 128x256, 16 warps (4x4), warp tile 32x64, BK=64,
//       4-stage cp.async pipeline, one sync per chunk
//       (wait -> sync -> compute -> issue), ldmatrix.x4 feeds,
//       mma.m16n8k16 f32 accum.  out[M,N] f32 = x @ W^T + bias.

#define KDIM 4096
#define NDIM 11008
#define MDIM 8192
#define BM 128
#define BN 256
#define BK 64                    // halves per k-chunk (128 B rows)
#define NCHUNKS (KDIM / BK)      // 64
#define THREADS 512
#define STAGES 4

#define A_STAGE_BYTES (BM * 128)                      // 16 KB
#define B_STAGE_BYTES (BN * 128)                      // 32 KB
#define STAGE_BYTES (A_STAGE_BYTES + B_STAGE_BYTES)   // 48 KB
#define SMEM_TOTAL (STAGES * STAGE_BYTES)             // 192 KB

__device__ __half g_xh[(size_t)MDIM * KDIM];   // 64 MB
__device__ __half g_wh[(size_t)NDIM * KDIM];   // 90 MB

// ---------------- prolog kernels ----------------

__global__ void convert_x_kernel(const float* __restrict__ x) {
    size_t i = (size_t)blockIdx.x * blockDim.x + threadIdx.x;  // one float4
    float4 v = ((const float4*)x)[i];
    __half2* o = (__half2*)g_xh;
    o[2 * i]     = __floats2half2_rn(v.x, v.y);
    o[2 * i + 1] = __floats2half2_rn(v.z, v.w);
}

__global__ void dequant_w_kernel(const int* __restrict__ wp,
                                 const float* __restrict__ scales) {
    size_t i = (size_t)blockIdx.x * blockDim.x + threadIdx.x;  // 4 int32 per thread
    size_t base = i * 4;
    int n  = (int)(base >> 11);        // K/2 = 2048 int32 per row
    int k2 = (int)(base & 2047);
    int4 v4 = ((const int4*)wp)[i];
    float s = scales[(n << 5) + (k2 >> 6)];   // 4 int32 never straddle a group (64 int32)
    __half2* o = (__half2*)g_wh + base;
    int vv[4] = {v4.x, v4.y, v4.z, v4.w};
#pragma unroll
    for (int j = 0; j < 4; j++) {
        int v = vv[j];
        float lo = (float)((v & 15) - 8) * s;
        float hi = (float)(((v >> 4) & 15) - 8) * s;
        o[j] = __floats2half2_rn(lo, hi);
    }
}

// ---------------- helpers ----------------

__device__ __forceinline__ uint32_t smem_u32(const void* p) {
    return (uint32_t)__cvta_generic_to_shared(p);
}
__device__ __forceinline__ uint32_t sw128(uint32_t off) {
    return off ^ ((off >> 3) & 0x70);
}
__device__ __forceinline__ void cp_async16(uint32_t saddr, const void* gaddr) {
    asm volatile("cp.async.cg.shared.global [%0], [%1], 16;"
                 :: "r"(saddr), "l"(gaddr));
}
__device__ __forceinline__ void cp_commit() {
    asm volatile("cp.async.commit_group;");
}
template <int N>
__device__ __forceinline__ void cp_wait() {
    asm volatile("cp.async.wait_group %0;" :: "n"(N));
}
__device__ __forceinline__ void ldsm4(uint32_t addr, uint32_t& r0, uint32_t& r1,
                                      uint32_t& r2, uint32_t& r3) {
    asm volatile("ldmatrix.sync.aligned.m8n8.x4.shared.b16 {%0,%1,%2,%3}, [%4];"
                 : "=r"(r0), "=r"(r1), "=r"(r2), "=r"(r3) : "r"(addr));
}
__device__ __forceinline__ void stg64_cs(void* p, float a, float b) {
    asm volatile("st.global.cs.v2.f32 [%0], {%1,%2};" :: "l"(p), "f"(a), "f"(b)
                 : "memory");
}

// ---------------- GEMM kernel ----------------

__global__ __launch_bounds__(THREADS, 1)
void q4_mma_kernel(const float* __restrict__ bias, float* __restrict__ out) {
    extern __shared__ char smem[];
    const uint32_t sbase = smem_u32(smem);

    const int tid  = threadIdx.x;
    const int wid  = tid >> 5;
    const int lane = tid & 31;
    const int g    = lane >> 2;
    const int tig  = lane & 3;
    const int warpM = wid >> 2;     // 0..3, 32 rows each
    const int warpN = wid & 3;      // 0..3, 64 cols each

    const int m0 = blockIdx.x * BM; // m fastest -> g_xh L2-resident per wave
    const int n0 = blockIdx.y * BN;

    // cp.async mapping: 16B chunks; 512 threads cover 64 rows x 8 segs
    const int crow = tid >> 3;      // 0..63
    const int cseg = tid & 7;       // 16B segment within 128B row
    const __half* aG = g_xh + (size_t)(m0 + crow) * KDIM + cseg * 8;
    const __half* bG = g_wh + (size_t)(n0 + crow) * KDIM + cseg * 8;

    uint32_t aS[2], bS[4];
#pragma unroll
    for (int i = 0; i < 2; i++)
        aS[i] = sw128((uint32_t)((crow + 64 * i) * 128 + cseg * 16));
#pragma unroll
    for (int i = 0; i < 4; i++)
        bS[i] = sw128((uint32_t)((crow + 64 * i) * 128 + cseg * 16));

    auto issue = [&](int kc) {
        const int st = kc % STAGES;
        const uint32_t sa = sbase + st * STAGE_BYTES;
        const uint32_t sb = sa + A_STAGE_BYTES;
        const size_t gofs = (size_t)kc * BK;
#pragma unroll
        for (int i = 0; i < 2; i++)
            cp_async16(sa + aS[i], aG + (size_t)(64 * i) * KDIM + gofs);
#pragma unroll
        for (int i = 0; i < 4; i++)
            cp_async16(sb + bS[i], bG + (size_t)(64 * i) * KDIM + gofs);
        cp_commit();
    };

    // ldmatrix address components (stage-relative)
    const uint32_t aRow = (uint32_t)(warpM * 32 + (lane & 15));
    const uint32_t aKof = (uint32_t)((lane >> 4) * 16);
    const uint32_t bRow = (uint32_t)(warpN * 64 + ((lane >> 4) << 3) + (lane & 7));
    const uint32_t bKof = (uint32_t)(((lane >> 3) & 1) * 16);

    float acc[2][8][4];
#pragma unroll
    for (int i = 0; i < 2; i++)
#pragma unroll
        for (int j = 0; j < 8; j++)
#pragma unroll
            for (int c = 0; c < 4; c++) acc[i][j][c] = 0.0f;

    // prologue: fill pipeline
    issue(0); issue(1); issue(2);

#pragma unroll 1
    for (int kc = 0; kc < NCHUNKS; kc++) {
        cp_wait<2>();
        __syncthreads();            // chunk kc visible; all warps past chunk kc-1

        const int st = kc % STAGES;
        const uint32_t sa = sbase + st * STAGE_BYTES;
        const uint32_t sb = sa + A_STAGE_BYTES;

#pragma unroll
        for (int ks = 0; ks < 4; ks++) {
            uint32_t a[2][4], b[4][4];
#pragma unroll
            for (int mi = 0; mi < 2; mi++) {
                uint32_t off = (aRow + mi * 16) * 128 + ks * 32 + aKof;
                ldsm4(sa + sw128(off), a[mi][0], a[mi][1], a[mi][2], a[mi][3]);
            }
#pragma unroll
            for (int nj = 0; nj < 4; nj++) {
                uint32_t off = (bRow + nj * 16) * 128 + ks * 32 + bKof;
                ldsm4(sb + sw128(off), b[nj][0], b[nj][1], b[nj][2], b[nj][3]);
            }
#pragma unroll
            for (int mi = 0; mi < 2; mi++) {
#pragma unroll
                for (int nj = 0; nj < 4; nj++) {
                    asm volatile(
                        "mma.sync.aligned.m16n8k16.row.col.f32.f16.f16.f32 "
                        "{%0,%1,%2,%3}, {%4,%5,%6,%7}, {%8,%9}, {%0,%1,%2,%3};\n"
                        : "+f"(acc[mi][2 * nj][0]), "+f"(acc[mi][2 * nj][1]),
                          "+f"(acc[mi][2 * nj][2]), "+f"(acc[mi][2 * nj][3])
                        : "r"(a[mi][0]), "r"(a[mi][1]), "r"(a[mi][2]), "r"(a[mi][3]),
                          "r"(b[nj][0]), "r"(b[nj][1]));
                    asm volatile(
                        "mma.sync.aligned.m16n8k16.row.col.f32.f16.f16.f32 "
                        "{%0,%1,%2,%3}, {%4,%5,%6,%7}, {%8,%9}, {%0,%1,%2,%3};\n"
                        : "+f"(acc[mi][2 * nj + 1][0]), "+f"(acc[mi][2 * nj + 1][1]),
                          "+f"(acc[mi][2 * nj + 1][2]), "+f"(acc[mi][2 * nj + 1][3])
                        : "r"(a[mi][0]), "r"(a[mi][1]), "r"(a[mi][2]), "r"(a[mi][3]),
                          "r"(b[nj][2]), "r"(b[nj][3]));
                }
            }
        }
        // issue AFTER compute: contiguous burst while tensor pipe drains;
        // refills stage (kc-1)%4, vacated at the sync above.
        if (kc + 3 < NCHUNKS) issue(kc + 3);
    }

    // ---- epilogue: add bias, write f32 (streaming, evict-first) ----
#pragma unroll
    for (int mi = 0; mi < 2; mi++) {
        const int row = m0 + warpM * 32 + mi * 16 + g;
#pragma unroll
        for (int nj = 0; nj < 8; nj++) {
            const int col = n0 + warpN * 64 + nj * 8 + tig * 2;
            float2 bb = *(const float2*)(bias + col);
            stg64_cs(out + (size_t)row * NDIM + col,
                     acc[mi][nj][0] + bb.x, acc[mi][nj][1] + bb.y);
            stg64_cs(out + (size_t)(row + 8) * NDIM + col,
                     acc[mi][nj][2] + bb.x, acc[mi][nj][3] + bb.y);
        }
    }
}

// ---------------- launcher ----------------

extern "C" void kernel_launch(void* const* d_in, const int* in_sizes, int n_in,
                              void* d_out, int out_size)
{
    const float* x      = (const float*)d_in[0];
    const int*   wp     = (const int*)d_in[1];
    const float* scales = (const float*)d_in[2];
    const float* bias   = (const float*)d_in[3];
    float*       out    = (float*)d_out;

    convert_x_kernel<<<(MDIM * (size_t)KDIM / 4) / 256, 256>>>(x);
    dequant_w_kernel<<<(NDIM * (size_t)(KDIM / 2) / 4) / 256, 256>>>(wp, scales);

    static bool attr_set = false;
    if (!attr_set) {
        cudaFuncSetAttribute(q4_mma_kernel,
                             cudaFuncAttributeMaxDynamicSharedMemorySize, SMEM_TOTAL);
        attr_set = true;
    }
    dim3 grid(MDIM / BM, NDIM / BN);   // (64, 43), m fastest
    q4_mma_kernel<<<grid, THREADS, SMEM_TOTAL>>>(bias, out);
}